// round 3
// baseline (speedup 1.0000x reference)
#include <cuda_runtime.h>
#include <math.h>
#include <float.h>

#define N_ROWS   16384
#define DIM      7168
#define N_EXP    256
#define N_GROUPS 8
#define N_TOPK_GROUP 4
#define TOPK     8
#define ROUTED_SCALE 2.5f

// scratch: original = sigmoid(x @ W^T), [N_ROWS, N_EXP] fp32 (16.7 MB)
__device__ float g_orig[(size_t)N_ROWS * N_EXP];

// ---------------------------------------------------------------------------
// GEMM + sigmoid epilogue.  BM=128, BN=128, BK=16, 256 threads, 8x8 microtile.
// x: [N_ROWS, DIM] row-major, W: [N_EXP, DIM] row-major (both K-major).
// ---------------------------------------------------------------------------
__global__ __launch_bounds__(256, 2)
void gemm_sigmoid_kernel(const float* __restrict__ x, const float* __restrict__ W) {
    const int BM = 128, BN = 128, BK = 16;
    __shared__ float As[BK][BM];   // transposed: As[k][m]
    __shared__ float Bs[BK][BN];   // transposed: Bs[k][n]

    const int tid = threadIdx.x;
    const int m0  = blockIdx.x * BM;
    const int n0  = blockIdx.y * BN;
    const int tm  = tid >> 4;       // 0..15
    const int tn  = tid & 15;       // 0..15

    float acc[8][8];
#pragma unroll
    for (int i = 0; i < 8; i++)
#pragma unroll
        for (int j = 0; j < 8; j++) acc[i][j] = 0.f;

    // load mapping: 128x16 floats = 512 float4; 256 threads -> 2 float4 each
    const int lrow = tid >> 2;          // 0..63
    const int lcol = (tid & 3) << 2;    // 0,4,8,12

    for (int k0 = 0; k0 < DIM; k0 += BK) {
#pragma unroll
        for (int half = 0; half < 2; half++) {
            const int r = lrow + half * 64;
            float4 v = *reinterpret_cast<const float4*>(
                &x[(size_t)(m0 + r) * DIM + k0 + lcol]);
            As[lcol + 0][r] = v.x;
            As[lcol + 1][r] = v.y;
            As[lcol + 2][r] = v.z;
            As[lcol + 3][r] = v.w;
        }
#pragma unroll
        for (int half = 0; half < 2; half++) {
            const int r = lrow + half * 64;
            float4 v = *reinterpret_cast<const float4*>(
                &W[(size_t)(n0 + r) * DIM + k0 + lcol]);
            Bs[lcol + 0][r] = v.x;
            Bs[lcol + 1][r] = v.y;
            Bs[lcol + 2][r] = v.z;
            Bs[lcol + 3][r] = v.w;
        }
        __syncthreads();

#pragma unroll
        for (int k = 0; k < BK; k++) {
            float4 a0 = *reinterpret_cast<const float4*>(&As[k][tm * 8]);
            float4 a1 = *reinterpret_cast<const float4*>(&As[k][tm * 8 + 4]);
            float4 b0 = *reinterpret_cast<const float4*>(&Bs[k][tn * 8]);
            float4 b1 = *reinterpret_cast<const float4*>(&Bs[k][tn * 8 + 4]);
            float a[8] = {a0.x, a0.y, a0.z, a0.w, a1.x, a1.y, a1.z, a1.w};
            float b[8] = {b0.x, b0.y, b0.z, b0.w, b1.x, b1.y, b1.z, b1.w};
#pragma unroll
            for (int i = 0; i < 8; i++)
#pragma unroll
                for (int j = 0; j < 8; j++)
                    acc[i][j] = fmaf(a[i], b[j], acc[i][j]);
        }
        __syncthreads();
    }

#pragma unroll
    for (int i = 0; i < 8; i++) {
        const int row = m0 + tm * 8 + i;
#pragma unroll
        for (int j = 0; j < 8; j++) {
            const int col = n0 + tn * 8 + j;
            float o = 1.0f / (1.0f + expf(-acc[i][j]));
            g_orig[(size_t)row * N_EXP + col] = o;
        }
    }
}

// ---------------------------------------------------------------------------
// Routing: one block (256 threads) per row. warp == group (8 groups x 32).
// ---------------------------------------------------------------------------
__global__ __launch_bounds__(256)
void routing_kernel(const float* __restrict__ bias,
                    float* __restrict__ out_w, float* __restrict__ out_i) {
    const int row  = blockIdx.x;
    const int e    = threadIdx.x;
    const int lane = e & 31;
    const int grp  = e >> 5;

    const float orig = g_orig[(size_t)row * N_EXP + e];
    const float s    = orig + bias[e];

    // --- top-2 sum within group (one warp per group) ---
    float m1 = s;
#pragma unroll
    for (int off = 16; off; off >>= 1)
        m1 = fmaxf(m1, __shfl_xor_sync(0xffffffffu, m1, off));
    unsigned ballot = __ballot_sync(0xffffffffu, s == m1);
    int firstlane = __ffs(ballot) - 1;
    float v2 = (lane == firstlane) ? -FLT_MAX : s;
    float m2 = v2;
#pragma unroll
    for (int off = 16; off; off >>= 1)
        m2 = fmaxf(m2, __shfl_xor_sync(0xffffffffu, m2, off));

    __shared__ float gscore[N_GROUPS];
    __shared__ int   keep[N_GROUPS];
    if (lane == 0) gscore[grp] = m1 + m2;
    if (e < N_GROUPS) keep[e] = 0;
    __syncthreads();

    // --- pick top-4 groups (serial, ties -> lower index, matches lax.top_k) ---
    if (e == 0) {
        float tmp[N_GROUPS];
#pragma unroll
        for (int g = 0; g < N_GROUPS; g++) tmp[g] = gscore[g];
        for (int t = 0; t < N_TOPK_GROUP; t++) {
            int best = 0;
            for (int g = 1; g < N_GROUPS; g++)
                if (tmp[g] > tmp[best]) best = g;
            keep[best] = 1;
            tmp[best] = -FLT_MAX;
        }
    }
    __syncthreads();

    float myv = keep[grp] ? s : -FLT_MAX;
    int   myi = e;

    __shared__ float red_v[8];
    __shared__ int   red_i[8];
    __shared__ float sel_w[TOPK];
    __shared__ int   sel_i[TOPK];

    // --- iterative block-wide top-8 (value desc, ties -> lower index) ---
    for (int t = 0; t < TOPK; t++) {
        float wv = myv; int wi = myi;
#pragma unroll
        for (int off = 16; off; off >>= 1) {
            float ov = __shfl_xor_sync(0xffffffffu, wv, off);
            int   oi = __shfl_xor_sync(0xffffffffu, wi, off);
            if (ov > wv || (ov == wv && oi < wi)) { wv = ov; wi = oi; }
        }
        if (lane == 0) { red_v[grp] = wv; red_i[grp] = wi; }
        __syncthreads();
        if (e == 0) {
            float bv = red_v[0]; int bi = red_i[0];
#pragma unroll
            for (int g = 1; g < 8; g++)
                if (red_v[g] > bv || (red_v[g] == bv && red_i[g] < bi)) {
                    bv = red_v[g]; bi = red_i[g];
                }
            sel_i[t] = bi;
            sel_w[t] = g_orig[(size_t)row * N_EXP + bi];  // weight from ORIGINAL (no bias)
        }
        __syncthreads();
        if (e == sel_i[t]) myv = -FLT_MAX;
        __syncthreads();
    }

    if (e == 0) {
        float sum = 0.f;
#pragma unroll
        for (int t = 0; t < TOPK; t++) sum += sel_w[t];
        const float scl = ROUTED_SCALE / sum;
#pragma unroll
        for (int t = 0; t < TOPK; t++) {
            out_w[(size_t)row * TOPK + t] = sel_w[t] * scl;
            out_i[(size_t)row * TOPK + t] = (float)sel_i[t];
        }
    }
}

extern "C" void kernel_launch(void* const* d_in, const int* in_sizes, int n_in,
                              void* d_out, int out_size) {
    const float* x = (const float*)d_in[0];   // [16384, 7168]
    const float* W = (const float*)d_in[1];   // [256, 7168]
    const float* b = (const float*)d_in[2];   // [256]
    float* out = (float*)d_out;               // [N*8 weights][N*8 indices-as-float]

    dim3 grid(N_ROWS / 128, N_EXP / 128);
    gemm_sigmoid_kernel<<<grid, 256>>>(x, W);
    routing_kernel<<<N_ROWS, 256>>>(b, out, out + (size_t)N_ROWS * TOPK);
}

// round 6
// speedup vs baseline: 1.8925x; 1.8925x over previous
#include <cuda_runtime.h>
#include <cuda_fp16.h>
#include <math.h>
#include <float.h>
#include <stdint.h>

#define N_ROWS   16384
#define DIM      7168
#define N_EXP    256
#define N_GROUPS 8
#define N_TOPK_GROUP 4
#define TOPK     8
#define ROUTED_SCALE 2.5f

#define M_TILE 128
#define N_TILE 128
#define K_TILE 64                    // fp16 elems -> 128 bytes/row (SW128 atom)
#define N_KTILES (DIM / K_TILE)      // 112
#define TILE_BYTES (M_TILE * 128)    // 16384 bytes per (split,stage) tile
#define SMEM_DYN_BYTES (8 * TILE_BYTES + 1024)

#define SX 64.0f                     // x scale
#define SW 512.0f                    // W scale
#define INV_S (1.0f / 32768.0f)      // 1/(SX*SW)

// scratch: original = sigmoid(x @ W^T), [N_ROWS, N_EXP] fp32 (16.7 MB)
__device__ float g_orig[(size_t)N_ROWS * N_EXP];

__device__ __forceinline__ uint32_t smem_u32(const void* p) {
    uint32_t a;
    asm("{ .reg .u64 t; cvta.to.shared.u64 t, %1; cvt.u32.u64 %0, t; }"
        : "=r"(a) : "l"(p));
    return a;
}

// 2-way fp16 split of a scaled float2: v = h + m + O(2^-22 |v|)
__device__ __forceinline__ void split2(float vx, float vy, uint32_t& h, uint32_t& m) {
    float2 v = make_float2(vx, vy);
    __half2 h2 = __float22half2_rn(v);
    float2 hf = __half22float2(h2);
    __half2 m2 = __float22half2_rn(make_float2(v.x - hf.x, v.y - hf.y));
    h = *reinterpret_cast<uint32_t*>(&h2);
    m = *reinterpret_cast<uint32_t*>(&m2);
}

__device__ __forceinline__ void ldmatrix_x4(uint32_t* f, uint32_t addr) {
    asm volatile("ldmatrix.sync.aligned.m8n8.x4.shared.b16 {%0,%1,%2,%3}, [%4];"
                 : "=r"(f[0]), "=r"(f[1]), "=r"(f[2]), "=r"(f[3]) : "r"(addr));
}

// D = A*B + C  (C is the persistent zero regs -> starts a fresh chain)
__device__ __forceinline__ void mma_f16_init(float* d, const uint32_t* a,
                                             uint32_t b0, uint32_t b1,
                                             const float* z) {
    asm volatile(
        "mma.sync.aligned.m16n8k16.row.col.f32.f16.f16.f32 "
        "{%0,%1,%2,%3}, {%4,%5,%6,%7}, {%8,%9}, {%10,%11,%12,%13};"
        : "=f"(d[0]), "=f"(d[1]), "=f"(d[2]), "=f"(d[3])
        : "r"(a[0]), "r"(a[1]), "r"(a[2]), "r"(a[3]), "r"(b0), "r"(b1),
          "f"(z[0]), "f"(z[1]), "f"(z[2]), "f"(z[3]));
}

// D += A*B (chain continue)
__device__ __forceinline__ void mma_f16_acc(float* d, const uint32_t* a,
                                            uint32_t b0, uint32_t b1) {
    asm volatile(
        "mma.sync.aligned.m16n8k16.row.col.f32.f16.f16.f32 "
        "{%0,%1,%2,%3}, {%4,%5,%6,%7}, {%8,%9}, {%0,%1,%2,%3};"
        : "+f"(d[0]), "+f"(d[1]), "+f"(d[2]), "+f"(d[3])
        : "r"(a[0]), "r"(a[1]), "r"(a[2]), "r"(a[3]), "r"(b0), "r"(b1));
}

// ---------------------------------------------------------------------------
// GEMM (mma.sync fp16, 2-way split, 3 terms hh+hm+mh, RZ-safe flushed
// accumulation) + sigmoid epilogue.
// grid = 256: bid>>1 -> M tile, bid&1 -> N half. 256 threads, 8 warps.
// Warp w owns D[(w&1)*64 +: 64, (w>>1)*32 +: 32] of the 128x128 tile.
// ---------------------------------------------------------------------------
__global__ void __launch_bounds__(256, 1)
gate_gemm_kernel(const float* __restrict__ x, const float* __restrict__ W) {
    extern __shared__ char dsm_raw[];
    char* dsm = (char*)(((uintptr_t)dsm_raw + 1023) & ~(uintptr_t)1023);
    const uint32_t sbase = smem_u32(dsm);

    const int tid  = threadIdx.x;
    const int wid  = tid >> 5;
    const int lane = tid & 31;
    const int bid  = blockIdx.x;
    const int m0   = (bid >> 1) * M_TILE;
    const int n0   = (bid & 1) * N_TILE;

    // ---- loader mapping: thread handles rows (tid>>4)+16*i, chunk (tid&15) ----
    const float* aBase = x + (size_t)(m0 + (tid >> 4)) * DIM + (tid & 15) * 4;
    const float* bBase = W + (size_t)(n0 + (tid >> 4)) * DIM + (tid & 15) * 4;
    uint32_t off0 = (uint32_t)(tid >> 4) * 128u + (uint32_t)(tid & 15) * 8u;
    const uint32_t sw0 = off0 ^ ((off0 >> 3) & 0x70);

    // ---- mma lane addressing (SW128: swz(off) = off ^ ((row&7)<<4)) ----
    const int mrow = (wid & 1) * 64;
    const int ncol = (wid >> 1) * 32;
    const int lrow8 = ((lane >> 3) & 1) * 8 + (lane & 7);
    const uint32_t khalf = (uint32_t)(lane >> 4) * 16u;

    uint32_t aR[4], aX[4], bR[2], bX[2];
#pragma unroll
    for (int mt = 0; mt < 4; mt++) {
        const int r = mrow + mt * 16 + lrow8;
        aR[mt] = (uint32_t)r * 128u;
        aX[mt] = (uint32_t)(r & 7) << 4;
    }
#pragma unroll
    for (int bp = 0; bp < 2; bp++) {
        const int n = ncol + bp * 16 + lrow8;
        bR[bp] = (uint32_t)n * 128u;
        bX[bp] = (uint32_t)(n & 7) << 4;
    }

    float master[4][4][4];
#pragma unroll
    for (int mt = 0; mt < 4; mt++)
#pragma unroll
        for (int nt = 0; nt < 4; nt++)
#pragma unroll
            for (int r = 0; r < 4; r++) master[mt][nt][r] = 0.f;

    float zr[4] = {0.f, 0.f, 0.f, 0.f};   // persistent zero C operand

    float4 curA[8];
#pragma unroll
    for (int i = 0; i < 8; i++)
        curA[i] = *(const float4*)(aBase + (size_t)i * 16 * DIM);

    // SMEM slots: A(h)=st*2, A(m)=st*2+1 ; B(h)=4+st*2, B(m)=4+st*2+1
    for (int t = 0; t < N_KTILES; t++) {
        const int st = t & 1;
        char* aH = dsm + (st * 2 + 0) * TILE_BYTES;
        char* aM = dsm + (st * 2 + 1) * TILE_BYTES;
        char* bH = dsm + (4 + st * 2 + 0) * TILE_BYTES;
        char* bM = dsm + (4 + st * 2 + 1) * TILE_BYTES;

        // B direct loads (L2-resident working set)
        float4 vB[8];
        {
            const float* bsrc = bBase + (size_t)t * K_TILE;
#pragma unroll
            for (int i = 0; i < 8; i++)
                vB[i] = *(const float4*)(bsrc + (size_t)i * 16 * DIM);
        }

#pragma unroll
        for (int i = 0; i < 8; i++) {
            const uint32_t so = sw0 + (uint32_t)i * 2048u;
            float4 v = curA[i];
            uint2 H, M;
            split2(v.x * SX, v.y * SX, H.x, M.x);
            split2(v.z * SX, v.w * SX, H.y, M.y);
            *(uint2*)(aH + so) = H;
            *(uint2*)(aM + so) = M;
        }
#pragma unroll
        for (int i = 0; i < 8; i++) {
            const uint32_t so = sw0 + (uint32_t)i * 2048u;
            float4 v = vB[i];
            uint2 H, M;
            split2(v.x * SW, v.y * SW, H.x, M.x);
            split2(v.z * SW, v.w * SW, H.y, M.y);
            *(uint2*)(bH + so) = H;
            *(uint2*)(bM + so) = M;
        }

        // prefetch next A K-tile into registers
        if (t + 1 < N_KTILES) {
            const float* ap = aBase + (size_t)(t + 1) * K_TILE;
#pragma unroll
            for (int i = 0; i < 8; i++)
                curA[i] = *(const float4*)(ap + (size_t)i * 16 * DIM);
        }

        __syncthreads();

        // 3 terms: (sa,sb) = (h,h), (h,m), (m,h)
#pragma unroll
        for (int p = 0; p < 3; p++) {
            const uint32_t aT = sbase + (uint32_t)(st * 2 + (p == 2 ? 1 : 0)) * TILE_BYTES;
            const uint32_t bT = sbase + (uint32_t)(4 + st * 2 + (p == 1 ? 1 : 0)) * TILE_BYTES;
#pragma unroll
            for (int h2 = 0; h2 < 2; h2++) {
                float temp[4][4][4];
                // --- k-step 2*h2: start fresh chains (C = zero regs) ---
                {
                    const uint32_t kc = (uint32_t)(h2 * 2) * 32u + khalf;
                    uint32_t af[4][4], bf[2][4];
#pragma unroll
                    for (int mt = 0; mt < 4; mt++)
                        ldmatrix_x4(af[mt], aT + aR[mt] + (kc ^ aX[mt]));
#pragma unroll
                    for (int bp = 0; bp < 2; bp++)
                        ldmatrix_x4(bf[bp], bT + bR[bp] + (kc ^ bX[bp]));
#pragma unroll
                    for (int mt = 0; mt < 4; mt++)
#pragma unroll
                        for (int nt = 0; nt < 4; nt++)
                            mma_f16_init(temp[mt][nt], af[mt],
                                         bf[nt >> 1][nt & 1], bf[nt >> 1][2 + (nt & 1)], zr);
                }
                // --- k-step 2*h2+1: continue chains ---
                {
                    const uint32_t kc = (uint32_t)(h2 * 2 + 1) * 32u + khalf;
                    uint32_t af[4][4], bf[2][4];
#pragma unroll
                    for (int mt = 0; mt < 4; mt++)
                        ldmatrix_x4(af[mt], aT + aR[mt] + (kc ^ aX[mt]));
#pragma unroll
                    for (int bp = 0; bp < 2; bp++)
                        ldmatrix_x4(bf[bp], bT + bR[bp] + (kc ^ bX[bp]));
#pragma unroll
                    for (int mt = 0; mt < 4; mt++)
#pragma unroll
                        for (int nt = 0; nt < 4; nt++)
                            mma_f16_acc(temp[mt][nt], af[mt],
                                        bf[nt >> 1][nt & 1], bf[nt >> 1][2 + (nt & 1)]);
                }
                // --- flush span into RN fp32 master accumulators ---
#pragma unroll
                for (int mt = 0; mt < 4; mt++)
#pragma unroll
                    for (int nt = 0; nt < 4; nt++)
#pragma unroll
                        for (int r = 0; r < 4; r++)
                            master[mt][nt][r] += temp[mt][nt][r];
            }
        }
        // double buffer + next iteration's pre-compute __syncthreads suffice.
    }

    // ---- epilogue: unscale, sigmoid, store to g_orig ----
    const int gid = lane >> 2;
    const int tig = lane & 3;
#pragma unroll
    for (int mt = 0; mt < 4; mt++) {
#pragma unroll
        for (int nt = 0; nt < 4; nt++) {
            const int r0 = m0 + mrow + mt * 16 + gid;
            const int c  = n0 + ncol + nt * 8 + tig * 2;
            float2 v0, v1;
            v0.x = 1.0f / (1.0f + expf(-master[mt][nt][0] * INV_S));
            v0.y = 1.0f / (1.0f + expf(-master[mt][nt][1] * INV_S));
            v1.x = 1.0f / (1.0f + expf(-master[mt][nt][2] * INV_S));
            v1.y = 1.0f / (1.0f + expf(-master[mt][nt][3] * INV_S));
            *(float2*)(g_orig + (size_t)r0 * N_EXP + c)       = v0;
            *(float2*)(g_orig + (size_t)(r0 + 8) * N_EXP + c) = v1;
        }
    }
}

// ---------------------------------------------------------------------------
// Routing: one block (256 threads) per row. warp == group (8 groups x 32).
// (unchanged from passing kernel)
// ---------------------------------------------------------------------------
__global__ __launch_bounds__(256)
void routing_kernel(const float* __restrict__ bias,
                    float* __restrict__ out_w, float* __restrict__ out_i) {
    const int row  = blockIdx.x;
    const int e    = threadIdx.x;
    const int lane = e & 31;
    const int grp  = e >> 5;

    const float orig = g_orig[(size_t)row * N_EXP + e];
    const float s    = orig + bias[e];

    float m1 = s;
#pragma unroll
    for (int off = 16; off; off >>= 1)
        m1 = fmaxf(m1, __shfl_xor_sync(0xffffffffu, m1, off));
    unsigned ballot = __ballot_sync(0xffffffffu, s == m1);
    int firstlane = __ffs(ballot) - 1;
    float v2 = (lane == firstlane) ? -FLT_MAX : s;
    float m2 = v2;
#pragma unroll
    for (int off = 16; off; off >>= 1)
        m2 = fmaxf(m2, __shfl_xor_sync(0xffffffffu, m2, off));

    __shared__ float gscore[N_GROUPS];
    __shared__ int   keep[N_GROUPS];
    if (lane == 0) gscore[grp] = m1 + m2;
    if (e < N_GROUPS) keep[e] = 0;
    __syncthreads();

    if (e == 0) {
        float tmp[N_GROUPS];
#pragma unroll
        for (int g = 0; g < N_GROUPS; g++) tmp[g] = gscore[g];
        for (int t = 0; t < N_TOPK_GROUP; t++) {
            int best = 0;
            for (int g = 1; g < N_GROUPS; g++)
                if (tmp[g] > tmp[best]) best = g;
            keep[best] = 1;
            tmp[best] = -FLT_MAX;
        }
    }
    __syncthreads();

    float myv = keep[grp] ? s : -FLT_MAX;
    int   myi = e;

    __shared__ float red_v[8];
    __shared__ int   red_i[8];
    __shared__ float sel_w[TOPK];
    __shared__ int   sel_i[TOPK];

    for (int t = 0; t < TOPK; t++) {
        float wv = myv; int wi = myi;
#pragma unroll
        for (int off = 16; off; off >>= 1) {
            float ov = __shfl_xor_sync(0xffffffffu, wv, off);
            int   oi = __shfl_xor_sync(0xffffffffu, wi, off);
            if (ov > wv || (ov == wv && oi < wi)) { wv = ov; wi = oi; }
        }
        if (lane == 0) { red_v[grp] = wv; red_i[grp] = wi; }
        __syncthreads();
        if (e == 0) {
            float bv = red_v[0]; int bi = red_i[0];
#pragma unroll
            for (int g = 1; g < 8; g++)
                if (red_v[g] > bv || (red_v[g] == bv && red_i[g] < bi)) {
                    bv = red_v[g]; bi = red_i[g];
                }
            sel_i[t] = bi;
            sel_w[t] = g_orig[(size_t)row * N_EXP + bi];
        }
        __syncthreads();
        if (e == sel_i[t]) myv = -FLT_MAX;
        __syncthreads();
    }

    if (e == 0) {
        float sum = 0.f;
#pragma unroll
        for (int t = 0; t < TOPK; t++) sum += sel_w[t];
        const float scl = ROUTED_SCALE / sum;
#pragma unroll
        for (int t = 0; t < TOPK; t++) {
            out_w[(size_t)row * TOPK + t] = sel_w[t] * scl;
            out_i[(size_t)row * TOPK + t] = (float)sel_i[t];
        }
    }
}

extern "C" void kernel_launch(void* const* d_in, const int* in_sizes, int n_in,
                              void* d_out, int out_size) {
    const float* x = (const float*)d_in[0];   // [16384, 7168]
    const float* W = (const float*)d_in[1];   // [256, 7168]
    const float* b = (const float*)d_in[2];   // [256]
    float* out = (float*)d_out;               // [N*8 weights][N*8 indices-as-float]

    cudaFuncSetAttribute(gate_gemm_kernel,
                         cudaFuncAttributeMaxDynamicSharedMemorySize, SMEM_DYN_BYTES);
    gate_gemm_kernel<<<256, 256, SMEM_DYN_BYTES>>>(x, W);
    routing_kernel<<<N_ROWS, 256>>>(b, out, out + (size_t)N_ROWS * TOPK);
}

// round 7
// speedup vs baseline: 1.8974x; 1.0026x over previous
#include <cuda_runtime.h>
#include <cuda_fp16.h>
#include <math.h>
#include <float.h>
#include <stdint.h>

#define N_ROWS   16384
#define DIM      7168
#define N_EXP    256
#define N_GROUPS 8
#define N_TOPK_GROUP 4
#define TOPK     8
#define ROUTED_SCALE 2.5f

#define M_TILE 128
#define N_TILE 128
#define K_TILE 64                    // fp16 elems -> 128 bytes/row (SW128 atom)
#define N_KTILES (DIM / K_TILE)      // 112
#define TILE_BYTES (M_TILE * 128)    // 16384 bytes per (split,stage) tile
#define SMEM_DYN_BYTES (8 * TILE_BYTES + 1024)

#define SX 64.0f                     // x scale
#define SW 512.0f                    // W scale
#define INV_S (1.0f / 32768.0f)      // 1/(SX*SW)

// scratch: original = sigmoid(x @ W^T), [N_ROWS, N_EXP] fp32 (16.7 MB)
__device__ float g_orig[(size_t)N_ROWS * N_EXP];

__device__ __forceinline__ uint32_t smem_u32(const void* p) {
    uint32_t a;
    asm("{ .reg .u64 t; cvta.to.shared.u64 t, %1; cvt.u32.u64 %0, t; }"
        : "=r"(a) : "l"(p));
    return a;
}

// 2-way fp16 split of a scaled float2: v = h + m + O(2^-22 |v|)
__device__ __forceinline__ void split2(float vx, float vy, uint32_t& h, uint32_t& m) {
    float2 v = make_float2(vx, vy);
    __half2 h2 = __float22half2_rn(v);
    float2 hf = __half22float2(h2);
    __half2 m2 = __float22half2_rn(make_float2(v.x - hf.x, v.y - hf.y));
    h = *reinterpret_cast<uint32_t*>(&h2);
    m = *reinterpret_cast<uint32_t*>(&m2);
}

__device__ __forceinline__ void ldmatrix_x4(uint32_t* f, uint32_t addr) {
    asm volatile("ldmatrix.sync.aligned.m8n8.x4.shared.b16 {%0,%1,%2,%3}, [%4];"
                 : "=r"(f[0]), "=r"(f[1]), "=r"(f[2]), "=r"(f[3]) : "r"(addr));
}

// D = A*B + C  (C is the persistent zero regs -> starts a fresh chain)
__device__ __forceinline__ void mma_f16_init(float* d, const uint32_t* a,
                                             uint32_t b0, uint32_t b1,
                                             const float* z) {
    asm volatile(
        "mma.sync.aligned.m16n8k16.row.col.f32.f16.f16.f32 "
        "{%0,%1,%2,%3}, {%4,%5,%6,%7}, {%8,%9}, {%10,%11,%12,%13};"
        : "=f"(d[0]), "=f"(d[1]), "=f"(d[2]), "=f"(d[3])
        : "r"(a[0]), "r"(a[1]), "r"(a[2]), "r"(a[3]), "r"(b0), "r"(b1),
          "f"(z[0]), "f"(z[1]), "f"(z[2]), "f"(z[3]));
}

// D += A*B (chain continue)
__device__ __forceinline__ void mma_f16_acc(float* d, const uint32_t* a,
                                            uint32_t b0, uint32_t b1) {
    asm volatile(
        "mma.sync.aligned.m16n8k16.row.col.f32.f16.f16.f32 "
        "{%0,%1,%2,%3}, {%4,%5,%6,%7}, {%8,%9}, {%0,%1,%2,%3};"
        : "+f"(d[0]), "+f"(d[1]), "+f"(d[2]), "+f"(d[3])
        : "r"(a[0]), "r"(a[1]), "r"(a[2]), "r"(a[3]), "r"(b0), "r"(b1));
}

// ---------------------------------------------------------------------------
// GEMM (mma.sync fp16, 2-way split, 3 terms hh+hm+mh, RZ-safe flushed
// accumulation) + sigmoid epilogue.
// grid = 256: bid>>1 -> M tile, bid&1 -> N half. 256 threads, 8 warps.
// Warp w owns D[(w&1)*64 +: 64, (w>>1)*32 +: 32] of the 128x128 tile.
// ---------------------------------------------------------------------------
__global__ void __launch_bounds__(256, 1)
gate_gemm_kernel(const float* __restrict__ x, const float* __restrict__ W) {
    extern __shared__ char dsm_raw[];
    char* dsm = (char*)(((uintptr_t)dsm_raw + 1023) & ~(uintptr_t)1023);
    const uint32_t sbase = smem_u32(dsm);

    const int tid  = threadIdx.x;
    const int wid  = tid >> 5;
    const int lane = tid & 31;
    const int bid  = blockIdx.x;
    const int m0   = (bid >> 1) * M_TILE;
    const int n0   = (bid & 1) * N_TILE;

    // ---- loader mapping: thread handles rows (tid>>4)+16*i, chunk (tid&15) ----
    const float* aBase = x + (size_t)(m0 + (tid >> 4)) * DIM + (tid & 15) * 4;
    const float* bBase = W + (size_t)(n0 + (tid >> 4)) * DIM + (tid & 15) * 4;
    uint32_t off0 = (uint32_t)(tid >> 4) * 128u + (uint32_t)(tid & 15) * 8u;
    const uint32_t sw0 = off0 ^ ((off0 >> 3) & 0x70);

    // ---- mma lane addressing (SW128: swz(off) = off ^ ((row&7)<<4)) ----
    const int mrow = (wid & 1) * 64;
    const int ncol = (wid >> 1) * 32;
    const int lrow8 = ((lane >> 3) & 1) * 8 + (lane & 7);
    const uint32_t khalf = (uint32_t)(lane >> 4) * 16u;

    uint32_t aR[4], aX[4], bR[2], bX[2];
#pragma unroll
    for (int mt = 0; mt < 4; mt++) {
        const int r = mrow + mt * 16 + lrow8;
        aR[mt] = (uint32_t)r * 128u;
        aX[mt] = (uint32_t)(r & 7) << 4;
    }
#pragma unroll
    for (int bp = 0; bp < 2; bp++) {
        const int n = ncol + bp * 16 + lrow8;
        bR[bp] = (uint32_t)n * 128u;
        bX[bp] = (uint32_t)(n & 7) << 4;
    }

    float master[4][4][4];
#pragma unroll
    for (int mt = 0; mt < 4; mt++)
#pragma unroll
        for (int nt = 0; nt < 4; nt++)
#pragma unroll
            for (int r = 0; r < 4; r++) master[mt][nt][r] = 0.f;

    float zr[4] = {0.f, 0.f, 0.f, 0.f};   // persistent zero C operand

    float4 curA[8];
#pragma unroll
    for (int i = 0; i < 8; i++)
        curA[i] = *(const float4*)(aBase + (size_t)i * 16 * DIM);

    // SMEM slots: A(h)=st*2, A(m)=st*2+1 ; B(h)=4+st*2, B(m)=4+st*2+1
    for (int t = 0; t < N_KTILES; t++) {
        const int st = t & 1;
        char* aH = dsm + (st * 2 + 0) * TILE_BYTES;
        char* aM = dsm + (st * 2 + 1) * TILE_BYTES;
        char* bH = dsm + (4 + st * 2 + 0) * TILE_BYTES;
        char* bM = dsm + (4 + st * 2 + 1) * TILE_BYTES;

        // B direct loads (L2-resident working set)
        float4 vB[8];
        {
            const float* bsrc = bBase + (size_t)t * K_TILE;
#pragma unroll
            for (int i = 0; i < 8; i++)
                vB[i] = *(const float4*)(bsrc + (size_t)i * 16 * DIM);
        }

#pragma unroll
        for (int i = 0; i < 8; i++) {
            const uint32_t so = sw0 + (uint32_t)i * 2048u;
            float4 v = curA[i];
            uint2 H, M;
            split2(v.x * SX, v.y * SX, H.x, M.x);
            split2(v.z * SX, v.w * SX, H.y, M.y);
            *(uint2*)(aH + so) = H;
            *(uint2*)(aM + so) = M;
        }
#pragma unroll
        for (int i = 0; i < 8; i++) {
            const uint32_t so = sw0 + (uint32_t)i * 2048u;
            float4 v = vB[i];
            uint2 H, M;
            split2(v.x * SW, v.y * SW, H.x, M.x);
            split2(v.z * SW, v.w * SW, H.y, M.y);
            *(uint2*)(bH + so) = H;
            *(uint2*)(bM + so) = M;
        }

        // prefetch next A K-tile into registers
        if (t + 1 < N_KTILES) {
            const float* ap = aBase + (size_t)(t + 1) * K_TILE;
#pragma unroll
            for (int i = 0; i < 8; i++)
                curA[i] = *(const float4*)(ap + (size_t)i * 16 * DIM);
        }

        __syncthreads();

        // 3 terms: (sa,sb) = (h,h), (h,m), (m,h)
#pragma unroll
        for (int p = 0; p < 3; p++) {
            const uint32_t aT = sbase + (uint32_t)(st * 2 + (p == 2 ? 1 : 0)) * TILE_BYTES;
            const uint32_t bT = sbase + (uint32_t)(4 + st * 2 + (p == 1 ? 1 : 0)) * TILE_BYTES;
#pragma unroll
            for (int h2 = 0; h2 < 2; h2++) {
                float temp[4][4][4];
                // --- k-step 2*h2: start fresh chains (C = zero regs) ---
                {
                    const uint32_t kc = (uint32_t)(h2 * 2) * 32u + khalf;
                    uint32_t af[4][4], bf[2][4];
#pragma unroll
                    for (int mt = 0; mt < 4; mt++)
                        ldmatrix_x4(af[mt], aT + aR[mt] + (kc ^ aX[mt]));
#pragma unroll
                    for (int bp = 0; bp < 2; bp++)
                        ldmatrix_x4(bf[bp], bT + bR[bp] + (kc ^ bX[bp]));
#pragma unroll
                    for (int mt = 0; mt < 4; mt++)
#pragma unroll
                        for (int nt = 0; nt < 4; nt++)
                            mma_f16_init(temp[mt][nt], af[mt],
                                         bf[nt >> 1][nt & 1], bf[nt >> 1][2 + (nt & 1)], zr);
                }
                // --- k-step 2*h2+1: continue chains ---
                {
                    const uint32_t kc = (uint32_t)(h2 * 2 + 1) * 32u + khalf;
                    uint32_t af[4][4], bf[2][4];
#pragma unroll
                    for (int mt = 0; mt < 4; mt++)
                        ldmatrix_x4(af[mt], aT + aR[mt] + (kc ^ aX[mt]));
#pragma unroll
                    for (int bp = 0; bp < 2; bp++)
                        ldmatrix_x4(bf[bp], bT + bR[bp] + (kc ^ bX[bp]));
#pragma unroll
                    for (int mt = 0; mt < 4; mt++)
#pragma unroll
                        for (int nt = 0; nt < 4; nt++)
                            mma_f16_acc(temp[mt][nt], af[mt],
                                        bf[nt >> 1][nt & 1], bf[nt >> 1][2 + (nt & 1)]);
                }
                // --- flush span into RN fp32 master accumulators ---
#pragma unroll
                for (int mt = 0; mt < 4; mt++)
#pragma unroll
                    for (int nt = 0; nt < 4; nt++)
#pragma unroll
                        for (int r = 0; r < 4; r++)
                            master[mt][nt][r] += temp[mt][nt][r];
            }
        }
        // double buffer + next iteration's pre-compute __syncthreads suffice.
    }

    // ---- epilogue: unscale, sigmoid, store to g_orig ----
    const int gid = lane >> 2;
    const int tig = lane & 3;
#pragma unroll
    for (int mt = 0; mt < 4; mt++) {
#pragma unroll
        for (int nt = 0; nt < 4; nt++) {
            const int r0 = m0 + mrow + mt * 16 + gid;
            const int c  = n0 + ncol + nt * 8 + tig * 2;
            float2 v0, v1;
            v0.x = 1.0f / (1.0f + expf(-master[mt][nt][0] * INV_S));
            v0.y = 1.0f / (1.0f + expf(-master[mt][nt][1] * INV_S));
            v1.x = 1.0f / (1.0f + expf(-master[mt][nt][2] * INV_S));
            v1.y = 1.0f / (1.0f + expf(-master[mt][nt][3] * INV_S));
            *(float2*)(g_orig + (size_t)r0 * N_EXP + c)       = v0;
            *(float2*)(g_orig + (size_t)(r0 + 8) * N_EXP + c) = v1;
        }
    }
}

// ---------------------------------------------------------------------------
// Routing: one block (256 threads) per row. warp == group (8 groups x 32).
// (unchanged from passing kernel)
// ---------------------------------------------------------------------------
__global__ __launch_bounds__(256)
void routing_kernel(const float* __restrict__ bias,
                    float* __restrict__ out_w, float* __restrict__ out_i) {
    const int row  = blockIdx.x;
    const int e    = threadIdx.x;
    const int lane = e & 31;
    const int grp  = e >> 5;

    const float orig = g_orig[(size_t)row * N_EXP + e];
    const float s    = orig + bias[e];

    float m1 = s;
#pragma unroll
    for (int off = 16; off; off >>= 1)
        m1 = fmaxf(m1, __shfl_xor_sync(0xffffffffu, m1, off));
    unsigned ballot = __ballot_sync(0xffffffffu, s == m1);
    int firstlane = __ffs(ballot) - 1;
    float v2 = (lane == firstlane) ? -FLT_MAX : s;
    float m2 = v2;
#pragma unroll
    for (int off = 16; off; off >>= 1)
        m2 = fmaxf(m2, __shfl_xor_sync(0xffffffffu, m2, off));

    __shared__ float gscore[N_GROUPS];
    __shared__ int   keep[N_GROUPS];
    if (lane == 0) gscore[grp] = m1 + m2;
    if (e < N_GROUPS) keep[e] = 0;
    __syncthreads();

    if (e == 0) {
        float tmp[N_GROUPS];
#pragma unroll
        for (int g = 0; g < N_GROUPS; g++) tmp[g] = gscore[g];
        for (int t = 0; t < N_TOPK_GROUP; t++) {
            int best = 0;
            for (int g = 1; g < N_GROUPS; g++)
                if (tmp[g] > tmp[best]) best = g;
            keep[best] = 1;
            tmp[best] = -FLT_MAX;
        }
    }
    __syncthreads();

    float myv = keep[grp] ? s : -FLT_MAX;
    int   myi = e;

    __shared__ float red_v[8];
    __shared__ int   red_i[8];
    __shared__ float sel_w[TOPK];
    __shared__ int   sel_i[TOPK];

    for (int t = 0; t < TOPK; t++) {
        float wv = myv; int wi = myi;
#pragma unroll
        for (int off = 16; off; off >>= 1) {
            float ov = __shfl_xor_sync(0xffffffffu, wv, off);
            int   oi = __shfl_xor_sync(0xffffffffu, wi, off);
            if (ov > wv || (ov == wv && oi < wi)) { wv = ov; wi = oi; }
        }
        if (lane == 0) { red_v[grp] = wv; red_i[grp] = wi; }
        __syncthreads();
        if (e == 0) {
            float bv = red_v[0]; int bi = red_i[0];
#pragma unroll
            for (int g = 1; g < 8; g++)
                if (red_v[g] > bv || (red_v[g] == bv && red_i[g] < bi)) {
                    bv = red_v[g]; bi = red_i[g];
                }
            sel_i[t] = bi;
            sel_w[t] = g_orig[(size_t)row * N_EXP + bi];
        }
        __syncthreads();
        if (e == sel_i[t]) myv = -FLT_MAX;
        __syncthreads();
    }

    if (e == 0) {
        float sum = 0.f;
#pragma unroll
        for (int t = 0; t < TOPK; t++) sum += sel_w[t];
        const float scl = ROUTED_SCALE / sum;
#pragma unroll
        for (int t = 0; t < TOPK; t++) {
            out_w[(size_t)row * TOPK + t] = sel_w[t] * scl;
            out_i[(size_t)row * TOPK + t] = (float)sel_i[t];
        }
    }
}

extern "C" void kernel_launch(void* const* d_in, const int* in_sizes, int n_in,
                              void* d_out, int out_size) {
    const float* x = (const float*)d_in[0];   // [16384, 7168]
    const float* W = (const float*)d_in[1];   // [256, 7168]
    const float* b = (const float*)d_in[2];   // [256]
    float* out = (float*)d_out;               // [N*8 weights][N*8 indices-as-float]

    cudaFuncSetAttribute(gate_gemm_kernel,
                         cudaFuncAttributeMaxDynamicSharedMemorySize, SMEM_DYN_BYTES);
    gate_gemm_kernel<<<256, 256, SMEM_DYN_BYTES>>>(x, W);
    routing_kernel<<<N_ROWS, 256>>>(b, out, out + (size_t)N_ROWS * TOPK);
}